// round 11
// baseline (speedup 1.0000x reference)
#include <cuda_runtime.h>
#include <cuda_bf16.h>

#define BINS 10
#define TPB  256
#define CTAS_PER_SM 7
#define GRID (148 * CTAS_PER_SM)

// __device__ globals zero-initialized at load; last block resets them after
// finalizing -> every launch / graph replay starts clean. Single launch node.
__device__ double             g_loss_sum[BINS];
__device__ unsigned long long g_count[BINS];
__device__ unsigned int       g_ticket;

// One element's accumulate into the block histogram.
// Slot = b*TPB + tid: bank index is tid-determined regardless of bin ->
// conflict-free by construction.
__device__ __forceinline__ void ghm_elem(float2* __restrict__ acc, int tid,
                                         float xx, float tt)
{
    float g  = fabsf(xx - tt);
    int   b  = (int)(g * 9.9999f);          // g < 1 strictly -> b in [0,9]
    float l1 = __log2f(xx);
    float l2 = __log2f(1.0f - xx);
    float loss2 = fmaf(tt, l1 - l2, l2);    // scaled by -ln2 at finalize
    int addr = b * TPB + tid;
    float2 a = acc[addr];
    a.x += loss2;
    a.y += 1.0f;
    acc[addr] = a;
}

__global__ __launch_bounds__(TPB, CTAS_PER_SM)
void ghm_fused_kernel(const float4* __restrict__ x4,
                      const float4* __restrict__ t4,
                      const float*  __restrict__ x1,
                      const float*  __restrict__ t1,
                      int n4, int n, long long N,
                      float* __restrict__ out)
{
    __shared__ float2 acc[BINS * TPB];

    const int tid = threadIdx.x;
#pragma unroll
    for (int k = 0; k < BINS; k++)
        acc[k * TPB + tid] = make_float2(0.0f, 0.0f);
    __syncthreads();

    const int stride = gridDim.x * blockDim.x;
    int i = blockIdx.x * blockDim.x + tid;

    // 3-stage software pipeline: keep 2 iterations of loads (4x LDG.128) in flight.
    if (i < n4) {
        float4 xv0 = x4[i];
        float4 tv0 = t4[i];
        float4 xv1, tv1;
        bool have1 = (i + stride < n4);
        if (have1) { xv1 = x4[i + stride]; tv1 = t4[i + stride]; }

        for (; i + 2 * stride < n4; i += stride) {
            float4 xn = x4[i + 2 * stride];
            float4 tn = t4[i + 2 * stride];
            ghm_elem(acc, tid, xv0.x, tv0.x);
            ghm_elem(acc, tid, xv0.y, tv0.y);
            ghm_elem(acc, tid, xv0.z, tv0.z);
            ghm_elem(acc, tid, xv0.w, tv0.w);
            xv0 = xv1; tv0 = tv1;
            xv1 = xn;  tv1 = tn;
        }
        // drain
        ghm_elem(acc, tid, xv0.x, tv0.x);
        ghm_elem(acc, tid, xv0.y, tv0.y);
        ghm_elem(acc, tid, xv0.z, tv0.z);
        ghm_elem(acc, tid, xv0.w, tv0.w);
        if (have1) {
            ghm_elem(acc, tid, xv1.x, tv1.x);
            ghm_elem(acc, tid, xv1.y, tv1.y);
            ghm_elem(acc, tid, xv1.z, tv1.z);
            ghm_elem(acc, tid, xv1.w, tv1.w);
        }
    }

    // scalar tail (n % 4): block 0 only
    if (blockIdx.x == 0) {
        for (int k = n4 * 4 + tid; k < n; k += blockDim.x)
            ghm_elem(acc, tid, x1[k], t1[k]);
    }
    __syncthreads();

    // block tree reduction over tid for all bins
    for (int s = TPB / 2; s > 0; s >>= 1) {
        if (tid < s) {
#pragma unroll
            for (int k = 0; k < BINS; k++) {
                float2 a = acc[k * TPB + tid];
                float2 b = acc[k * TPB + tid + s];
                a.x += b.x; a.y += b.y;
                acc[k * TPB + tid] = a;
            }
        }
        __syncthreads();
    }

    if (tid < BINS) {
        float2 a = acc[tid * TPB];
        atomicAdd(&g_loss_sum[tid], (double)a.x);
        atomicAdd(&g_count[tid], (unsigned long long)(a.y + 0.5f));
    }

    // last-block finalize + reset (fused epilogue)
    __shared__ unsigned int s_is_last;
    if (tid == 0) {
        __threadfence();
        unsigned int prev = atomicAdd(&g_ticket, 1u);
        s_is_last = (prev == (unsigned int)gridDim.x - 1u) ? 1u : 0u;
    }
    __syncthreads();

    if (s_is_last && tid == 0) {
        __threadfence();                     // all blocks' atomics visible
        const double NEG_LN2 = -0.6931471805599453;
        float nonempty = 0.0f;
#pragma unroll
        for (int k = 0; k < BINS; k++)
            nonempty += (g_count[k] > 0ull) ? 1.0f : 0.0f;

        const float Nf = (float)N;
        double total = 0.0;
#pragma unroll
        for (int k = 0; k < BINS; k++) {
            float cntf = (float)g_count[k];              // match jnp f32 cast
            float gd   = fmaxf(cntf * nonempty, 1.0f);
            float beta = Nf / gd;
            total += (double)beta * (NEG_LN2 * g_loss_sum[k]);
        }
        out[0] = (float)(total / (double)N);

        // reset for next launch / graph replay
#pragma unroll
        for (int k = 0; k < BINS; k++) {
            g_loss_sum[k] = 0.0;
            g_count[k]    = 0ull;
        }
        __threadfence();
        g_ticket = 0u;
    }
}

extern "C" void kernel_launch(void* const* d_in, const int* in_sizes, int n_in,
                              void* d_out, int out_size)
{
    const float* x = (const float*)d_in[0];
    const float* t = (const float*)d_in[1];
    float* out = (float*)d_out;

    const int n  = in_sizes[0];
    const int n4 = n >> 2;

    int blocks = GRID;
    int needed = (n4 + TPB - 1) / TPB;
    if (needed < 1) needed = 1;
    if (blocks > needed) blocks = needed;

    ghm_fused_kernel<<<blocks, TPB>>>(
        (const float4*)x, (const float4*)t, x, t, n4, n, (long long)n, out);
}

// round 13
// speedup vs baseline: 1.3045x; 1.3045x over previous
#include <cuda_runtime.h>
#include <cuda_bf16.h>

#define BINS 10
#define TPB  256
#define CTAS_PER_SM 6
#define GRID (148 * CTAS_PER_SM)

// __device__ globals zero-initialized at load; last block resets them after
// finalizing -> every launch / graph replay starts clean. Single launch node.
__device__ double             g_loss_sum[BINS];
__device__ unsigned long long g_count[BINS];
__device__ unsigned int       g_ticket;

// One element's accumulate into the block histogram.
// Slot = b*TPB + tid: bank index is tid-determined regardless of bin ->
// conflict-free by construction.
__device__ __forceinline__ void ghm_elem(float2* __restrict__ acc, int tid,
                                         float xx, float tt)
{
    float g  = fabsf(xx - tt);
    int   b  = (int)(g * 9.9999f);          // g < 1 strictly -> b in [0,9]
    float l1 = __log2f(xx);
    float l2 = __log2f(1.0f - xx);
    float loss2 = fmaf(tt, l1 - l2, l2);    // scaled by -ln2 at finalize
    int addr = b * TPB + tid;
    float2 a = acc[addr];
    a.x += loss2;
    a.y += 1.0f;
    acc[addr] = a;
}

__global__ __launch_bounds__(TPB, CTAS_PER_SM)
void ghm_fused_kernel(const float4* __restrict__ x4,
                      const float4* __restrict__ t4,
                      const float*  __restrict__ x1,
                      const float*  __restrict__ t1,
                      int n4, int n, long long N,
                      float* __restrict__ out)
{
    __shared__ float2 acc[BINS * TPB];

    const int tid = threadIdx.x;
#pragma unroll
    for (int k = 0; k < BINS; k++)
        acc[k * TPB + tid] = make_float2(0.0f, 0.0f);
    __syncthreads();

    // Blocked-contiguous partitioning: each CTA owns one contiguous chunk of
    // float4s and walks it with stride TPB (4KB steps) -> sequential DRAM
    // pages per CTA, TLB reuse, steady LTS pressure. Warps stay coalesced.
    const int per = (n4 + gridDim.x - 1) / gridDim.x;
    const int beg = blockIdx.x * per;
    const int end = min(beg + per, n4);

    int i = beg + tid;

    // 3-stage software pipeline: keep 2 iterations of loads (4x LDG.128) in flight.
    if (i < end) {
        float4 xv0 = x4[i];
        float4 tv0 = t4[i];
        float4 xv1, tv1;
        bool have1 = (i + TPB < end);
        if (have1) { xv1 = x4[i + TPB]; tv1 = t4[i + TPB]; }

        for (; i + 2 * TPB < end; i += TPB) {
            float4 xn = x4[i + 2 * TPB];
            float4 tn = t4[i + 2 * TPB];
            ghm_elem(acc, tid, xv0.x, tv0.x);
            ghm_elem(acc, tid, xv0.y, tv0.y);
            ghm_elem(acc, tid, xv0.z, tv0.z);
            ghm_elem(acc, tid, xv0.w, tv0.w);
            xv0 = xv1; tv0 = tv1;
            xv1 = xn;  tv1 = tn;
        }
        // drain
        ghm_elem(acc, tid, xv0.x, tv0.x);
        ghm_elem(acc, tid, xv0.y, tv0.y);
        ghm_elem(acc, tid, xv0.z, tv0.z);
        ghm_elem(acc, tid, xv0.w, tv0.w);
        if (have1) {
            ghm_elem(acc, tid, xv1.x, tv1.x);
            ghm_elem(acc, tid, xv1.y, tv1.y);
            ghm_elem(acc, tid, xv1.z, tv1.z);
            ghm_elem(acc, tid, xv1.w, tv1.w);
        }
    }

    // scalar tail (n % 4): last block
    if (blockIdx.x == gridDim.x - 1) {
        for (int k = n4 * 4 + tid; k < n; k += blockDim.x)
            ghm_elem(acc, tid, x1[k], t1[k]);
    }
    __syncthreads();

    // block tree reduction over tid for all bins
    for (int s = TPB / 2; s > 0; s >>= 1) {
        if (tid < s) {
#pragma unroll
            for (int k = 0; k < BINS; k++) {
                float2 a = acc[k * TPB + tid];
                float2 b = acc[k * TPB + tid + s];
                a.x += b.x; a.y += b.y;
                acc[k * TPB + tid] = a;
            }
        }
        __syncthreads();
    }

    if (tid < BINS) {
        float2 a = acc[tid * TPB];
        atomicAdd(&g_loss_sum[tid], (double)a.x);
        atomicAdd(&g_count[tid], (unsigned long long)(a.y + 0.5f));
    }

    // last-block finalize + reset (fused epilogue)
    __shared__ unsigned int s_is_last;
    if (tid == 0) {
        __threadfence();
        unsigned int prev = atomicAdd(&g_ticket, 1u);
        s_is_last = (prev == (unsigned int)gridDim.x - 1u) ? 1u : 0u;
    }
    __syncthreads();

    if (s_is_last && tid == 0) {
        __threadfence();                     // all blocks' atomics visible
        const double NEG_LN2 = -0.6931471805599453;
        float nonempty = 0.0f;
#pragma unroll
        for (int k = 0; k < BINS; k++)
            nonempty += (g_count[k] > 0ull) ? 1.0f : 0.0f;

        const float Nf = (float)N;
        double total = 0.0;
#pragma unroll
        for (int k = 0; k < BINS; k++) {
            float cntf = (float)g_count[k];              // match jnp f32 cast
            float gd   = fmaxf(cntf * nonempty, 1.0f);
            float beta = Nf / gd;
            total += (double)beta * (NEG_LN2 * g_loss_sum[k]);
        }
        out[0] = (float)(total / (double)N);

        // reset for next launch / graph replay
#pragma unroll
        for (int k = 0; k < BINS; k++) {
            g_loss_sum[k] = 0.0;
            g_count[k]    = 0ull;
        }
        __threadfence();
        g_ticket = 0u;
    }
}

extern "C" void kernel_launch(void* const* d_in, const int* in_sizes, int n_in,
                              void* d_out, int out_size)
{
    const float* x = (const float*)d_in[0];
    const float* t = (const float*)d_in[1];
    float* out = (float*)d_out;

    const int n  = in_sizes[0];
    const int n4 = n >> 2;

    int blocks = GRID;
    int needed = (n4 + TPB - 1) / TPB;
    if (needed < 1) needed = 1;
    if (blocks > needed) blocks = needed;

    ghm_fused_kernel<<<blocks, TPB>>>(
        (const float4*)x, (const float4*)t, x, t, n4, n, (long long)n, out);
}